// round 11
// baseline (speedup 1.0000x reference)
#include <cuda_runtime.h>
#include <cstdint>

#define HW 16384

// ---------------- scratch (device globals; no allocations allowed) ----------
__device__ float g_xn  [(size_t)65536 * 256];
__device__ float g_qkv [(size_t)65536 * 768];
__device__ float g_xc  [(size_t)65536 * 256];
__device__ float g_lepe[(size_t)2 * 128 * 2 * 512 * 64];

// pixel index of window-local token s for branch br, window-local wl
__device__ __forceinline__ int pix_of(int br, int wl, int s) {
    int row, col;
    if (br == 0) { row = s >> 2;            col = wl * 4 + (s & 3); }
    else         { row = wl * 4 + (s >> 7); col = s & 127; }
    return row * 128 + col;
}

// ---------------- LayerNorm: x[B,C,H,W] -> xn[tok][C] ------------------------
__global__ __launch_bounds__(256) void ln_kernel(
    const float* __restrict__ x, const float* __restrict__ g,
    const float* __restrict__ be, float* __restrict__ xn)
{
    __shared__ float xt[256 * 33];
    int b  = blockIdx.x >> 9;
    int p0 = (blockIdx.x & 511) * 32;
    int tid = threadIdx.x, lane = tid & 31, wp = tid >> 5;
    const float* xb = x + (size_t)b * 256 * HW + p0;
#pragma unroll
    for (int it = 0; it < 32; it++) {
        int c = it * 8 + wp;
        xt[c * 33 + lane] = xb[(size_t)c * HW + lane];
    }
    __syncthreads();
    for (int u = 0; u < 4; u++) {
        int p = wp * 4 + u;
        float v[8], sum = 0.f, sq = 0.f;
#pragma unroll
        for (int k = 0; k < 8; k++) {
            float t = xt[(lane + 32 * k) * 33 + p];
            v[k] = t; sum += t; sq += t * t;
        }
#pragma unroll
        for (int o = 16; o; o >>= 1) {
            sum += __shfl_xor_sync(0xffffffffu, sum, o);
            sq  += __shfl_xor_sync(0xffffffffu, sq,  o);
        }
        float mu = sum * (1.f / 256.f);
        float rs = rsqrtf(sq * (1.f / 256.f) - mu * mu + 1e-4f);
        size_t tokb = ((size_t)b * HW + p0 + p) * 256;
#pragma unroll
        for (int k = 0; k < 8; k++) {
            int c = lane + 32 * k;
            xn[tokb + c] = (v[k] - mu) * rs * g[c] + be[c];
        }
    }
}

// ---------------- fp32 SGEMM: C[M,N] = A[M,K] @ B[K,N] (+bias[m]) -----------
// 128x128 block tile, 16 k-depth, 256 threads, 8x8 microtile, reg prefetch.
__global__ __launch_bounds__(256) void sgemm_kernel(
    const float* __restrict__ A, const float* __restrict__ B,
    float* __restrict__ C, const float* __restrict__ bias,
    int M, int N, int K, int lda, int ldb, int ldc,
    size_t sA, size_t sB, size_t sC)
{
    __shared__ float As[16 * 132];   // [k][m]
    __shared__ float Bs[16 * 132];   // [k][n]
    A += (size_t)blockIdx.z * sA;
    B += (size_t)blockIdx.z * sB;
    C += (size_t)blockIdx.z * sC;
    int m0 = blockIdx.y * 128, n0 = blockIdx.x * 128;
    int tid = threadIdx.x, tx = tid & 15, ty = tid >> 4;

    float4 pa[2], pb[2];
    auto loadg = [&](int k0) {
#pragma unroll
        for (int s = 0; s < 2; s++) {
            int f4 = tid + 256 * s;
            pa[s] = *(const float4*)&A[(size_t)(m0 + (f4 >> 2)) * lda + k0 + (f4 & 3) * 4];
            pb[s] = *(const float4*)&B[(size_t)(k0 + (f4 >> 5)) * ldb + n0 + (f4 & 31) * 4];
        }
    };
    auto store_s = [&]() {
#pragma unroll
        for (int s = 0; s < 2; s++) {
            int f4 = tid + 256 * s; int row = f4 >> 2, kq = f4 & 3;
            As[(kq * 4 + 0) * 132 + row] = pa[s].x;
            As[(kq * 4 + 1) * 132 + row] = pa[s].y;
            As[(kq * 4 + 2) * 132 + row] = pa[s].z;
            As[(kq * 4 + 3) * 132 + row] = pa[s].w;
            *(float4*)&Bs[(f4 >> 5) * 132 + (f4 & 31) * 4] = pb[s];
        }
    };

    float acc[8][8];
#pragma unroll
    for (int i = 0; i < 8; i++)
#pragma unroll
        for (int j = 0; j < 8; j++) acc[i][j] = 0.f;

    loadg(0); store_s(); __syncthreads();
    for (int k0 = 16; k0 <= K; k0 += 16) {
        if (k0 < K) loadg(k0);
#pragma unroll
        for (int k = 0; k < 16; k++) {
            float a[8], bv[8];
            *(float4*)&a[0]  = *(const float4*)&As[k * 132 + ty * 8];
            *(float4*)&a[4]  = *(const float4*)&As[k * 132 + ty * 8 + 4];
            *(float4*)&bv[0] = *(const float4*)&Bs[k * 132 + tx * 8];
            *(float4*)&bv[4] = *(const float4*)&Bs[k * 132 + tx * 8 + 4];
#pragma unroll
            for (int i = 0; i < 8; i++)
#pragma unroll
                for (int j = 0; j < 8; j++) acc[i][j] = fmaf(a[i], bv[j], acc[i][j]);
        }
        __syncthreads();
        if (k0 < K) { store_s(); __syncthreads(); }
    }
#pragma unroll
    for (int i = 0; i < 8; i++) {
        size_t m = m0 + ty * 8 + i;
        float bv = bias ? bias[m] : 0.f;
        float4 c0, c1;
        c0.x = acc[i][0] + bv; c0.y = acc[i][1] + bv;
        c0.z = acc[i][2] + bv; c0.w = acc[i][3] + bv;
        c1.x = acc[i][4] + bv; c1.y = acc[i][5] + bv;
        c1.z = acc[i][6] + bv; c1.w = acc[i][7] + bv;
        float* cp = &C[m * ldc + n0 + tx * 8];
        *(float4*)cp = c0; *(float4*)(cp + 4) = c1;
    }
}

// ---------------- LePE: depthwise 3x3 per window, both branches --------------
__global__ __launch_bounds__(256) void lepe_kernel(
    const float* __restrict__ qkv,
    const float* __restrict__ w1, const float* __restrict__ b1,
    const float* __restrict__ w2, const float* __restrict__ b2,
    float* __restrict__ lepe)
{
    extern __shared__ float vbuf[];   // [512][33]
    int br = blockIdx.x >> 7, win = blockIdx.x & 127;
    int b = win >> 5, wl = win & 31;
    const float* w  = br ? w2 : w1;
    const float* bb = br ? b2 : b1;
    int tid = threadIdx.x;
    int hsp = br ? 4 : 128, wsp = br ? 128 : 4;
    int voff = 512 + br * 128;

    for (int ch0 = 0; ch0 < 128; ch0 += 32) {
        __syncthreads();
        for (int idx = tid; idx < 512 * 32; idx += 256) {
            int s = idx >> 5, c = idx & 31;
            size_t tok = (size_t)b * HW + pix_of(br, wl, s);
            vbuf[s * 33 + c] = qkv[tok * 768 + voff + ch0 + c];
        }
        __syncthreads();
        int c = tid & 31, cf = ch0 + c;
        float wr[9];
#pragma unroll
        for (int kk = 0; kk < 9; kk++) wr[kk] = w[cf * 9 + kk];
        float bv = bb[cf];
        size_t obase = ((size_t)(br * 128 + win) * 2 + (cf & 1)) * 512 * 64 + (cf >> 1);
        int sb = (tid >> 5) * 64;
        for (int t = 0; t < 64; t++) {
            int s = sb + t;
            int i = br ? (s >> 7) : (s >> 2);
            int j = br ? (s & 127) : (s & 3);
            float acc = bv;
#pragma unroll
            for (int di = 0; di < 3; di++) {
                int ii = i + di - 1;
                if (ii < 0 || ii >= hsp) continue;
#pragma unroll
                for (int dj = 0; dj < 3; dj++) {
                    int jj = j + dj - 1;
                    if (jj < 0 || jj >= wsp) continue;
                    acc = fmaf(vbuf[(ii * wsp + jj) * 33 + c], wr[di * 3 + dj], acc);
                }
            }
            lepe[obase + (size_t)s * 64] = acc;
        }
    }
}

// ---------------- flash attention per (br, win, head, 128-query tile) --------
__global__ __launch_bounds__(256) void attn_kernel(
    const float* __restrict__ qkv, const float* __restrict__ lepe,
    float* __restrict__ xc)
{
    extern __shared__ float sm[];
    float* Qs = sm;                 // [128][65]
    float* Ks = Qs + 128 * 65;      // [64][65]
    float* Vs = Ks + 64 * 65;       // [64][65]
    float* Ps = Vs + 64 * 65;       // [128][65]
    int bx = blockIdx.x;
    int qt = bx & 3, head = (bx >> 2) & 1, win = (bx >> 3) & 127, br = bx >> 10;
    int b = win >> 5, wl = win & 31;
    int tid = threadIdx.x, cg = tid & 15, rg = tid >> 4;
    int coff = br * 128 + head;
    const float qscale = 0.08838834764831845f * 1.4426950408889634f; // SCALE*log2e

    for (int idx = tid; idx < 128 * 64; idx += 256) {
        int r = idx >> 6, d = idx & 63;
        size_t tok = (size_t)b * HW + pix_of(br, wl, qt * 128 + r);
        Qs[r * 65 + d] = qkv[tok * 768 + coff + d * 2] * qscale;
    }
    float o[8][4], m[8], l[8];
#pragma unroll
    for (int i = 0; i < 8; i++) {
        m[i] = -1e30f; l[i] = 0.f;
#pragma unroll
        for (int j = 0; j < 4; j++) o[i][j] = 0.f;
    }

    for (int kt = 0; kt < 8; kt++) {
        __syncthreads();   // previous PV done before overwriting Ks/Vs
        for (int idx = tid; idx < 64 * 64; idx += 256) {
            int t = idx >> 6, d = idx & 63;
            size_t tok = (size_t)b * HW + pix_of(br, wl, kt * 64 + t);
            const float* qp = qkv + tok * 768 + coff + d * 2;
            Ks[t * 65 + d] = qp[256];
            Vs[t * 65 + d] = qp[512];
        }
        __syncthreads();

        float sacc[8][4];
#pragma unroll
        for (int i = 0; i < 8; i++)
#pragma unroll
            for (int j = 0; j < 4; j++) sacc[i][j] = 0.f;
#pragma unroll 4
        for (int k = 0; k < 64; k++) {
            float kv[4];
#pragma unroll
            for (int j = 0; j < 4; j++) kv[j] = Ks[(cg * 4 + j) * 65 + k];
#pragma unroll
            for (int i = 0; i < 8; i++) {
                float qv = Qs[(rg * 8 + i) * 65 + k];
#pragma unroll
                for (int j = 0; j < 4; j++) sacc[i][j] = fmaf(qv, kv[j], sacc[i][j]);
            }
        }
        // online softmax (row groups of 16 threads; xor<=8 stays in half-warp)
#pragma unroll
        for (int i = 0; i < 8; i++) {
            float mx = fmaxf(fmaxf(sacc[i][0], sacc[i][1]), fmaxf(sacc[i][2], sacc[i][3]));
#pragma unroll
            for (int off = 8; off; off >>= 1) mx = fmaxf(mx, __shfl_xor_sync(0xffffffffu, mx, off));
            float mn = fmaxf(m[i], mx);
            float f = exp2f(m[i] - mn);
            m[i] = mn;
            float ps = 0.f, p[4];
#pragma unroll
            for (int j = 0; j < 4; j++) { p[j] = exp2f(sacc[i][j] - mn); ps += p[j]; }
#pragma unroll
            for (int off = 8; off; off >>= 1) ps += __shfl_xor_sync(0xffffffffu, ps, off);
            l[i] = l[i] * f + ps;
#pragma unroll
            for (int j = 0; j < 4; j++) { o[i][j] *= f; Ps[(rg * 8 + i) * 65 + cg * 4 + j] = p[j]; }
        }
        __syncthreads();
#pragma unroll 4
        for (int k = 0; k < 64; k++) {
            float vv[4];
#pragma unroll
            for (int j = 0; j < 4; j++) vv[j] = Vs[k * 65 + cg * 4 + j];
#pragma unroll
            for (int i = 0; i < 8; i++) {
                float pv = Ps[(rg * 8 + i) * 65 + k];
#pragma unroll
                for (int j = 0; j < 4; j++) o[i][j] = fmaf(pv, vv[j], o[i][j]);
            }
        }
    }
    // epilogue: /l, + lepe, write xc[b][c][pix]
    size_t lbase = ((size_t)(br * 128 + win) * 2 + head) * 512 * 64;
#pragma unroll
    for (int i = 0; i < 8; i++) {
        int s = qt * 128 + rg * 8 + i;
        float inv = 1.f / l[i];
        float4 lp = *(const float4*)&lepe[lbase + (size_t)s * 64 + cg * 4];
        int pv = pix_of(br, wl, s);
        size_t obase = (size_t)b * 256 * HW + pv;
        int c0 = br * 128 + (cg * 4) * 2 + head;
        xc[obase + (size_t)(c0    ) * HW] = o[i][0] * inv + lp.x;
        xc[obase + (size_t)(c0 + 2) * HW] = o[i][1] * inv + lp.y;
        xc[obase + (size_t)(c0 + 4) * HW] = o[i][2] * inv + lp.z;
        xc[obase + (size_t)(c0 + 6) * HW] = o[i][3] * inv + lp.w;
    }
}

// ---------------- launch ------------------------------------------------------
extern "C" void kernel_launch(void* const* d_in, const int* in_sizes, int n_in,
                              void* d_out, int out_size)
{
    const float* x    = (const float*)d_in[0];
    const float* lng  = (const float*)d_in[1];
    const float* lnb  = (const float*)d_in[2];
    const float* wqkv = (const float*)d_in[3];
    const float* lw1  = (const float*)d_in[4];
    const float* lb1  = (const float*)d_in[5];
    const float* lw2  = (const float*)d_in[6];
    const float* lb2  = (const float*)d_in[7];
    const float* pw   = (const float*)d_in[8];
    const float* pb   = (const float*)d_in[9];
    float* out = (float*)d_out;

    float *xn, *qkv, *xc, *lp;
    cudaGetSymbolAddress((void**)&xn,  g_xn);
    cudaGetSymbolAddress((void**)&qkv, g_qkv);
    cudaGetSymbolAddress((void**)&xc,  g_xc);
    cudaGetSymbolAddress((void**)&lp,  g_lepe);

    cudaFuncSetAttribute(attn_kernel, cudaFuncAttributeMaxDynamicSharedMemorySize, 384 * 65 * 4);
    cudaFuncSetAttribute(lepe_kernel, cudaFuncAttributeMaxDynamicSharedMemorySize, 512 * 33 * 4);

    // 1) LayerNorm -> xn[tok][256]
    ln_kernel<<<2048, 256>>>(x, lng, lnb, xn);
    // 2) qkv[tok][768] = xn @ w_qkv
    sgemm_kernel<<<dim3(6, 512, 1), 256>>>(xn, wqkv, qkv, nullptr,
        65536, 768, 256, 256, 768, 768, 0, 0, 0);
    // 3) LePE per (branch, window)
    lepe_kernel<<<256, 256, 512 * 33 * 4>>>(qkv, lw1, lb1, lw2, lb2, lp);
    // 4) attention -> xc[b][c][pix]
    attn_kernel<<<2048, 256, 384 * 65 * 4>>>(qkv, lp, xc);
    // 5) out[b][o][pix] = proj_w @ xc (+ proj_b), per-batch strided
    sgemm_kernel<<<dim3(128, 2, 4), 256>>>(pw, xc, out, pb,
        256, 16384, 256, 256, 16384, 16384, 0, (size_t)256 * HW, (size_t)256 * HW);
}

// round 12
// speedup vs baseline: 1.0030x; 1.0030x over previous
#include <cuda_runtime.h>
#include <cstdint>

#define HW 16384

// ---------------- scratch (device globals; no allocations allowed) ----------
__device__ float g_xn  [(size_t)65536 * 256];
__device__ float g_qkv [(size_t)65536 * 768];
__device__ float g_xc  [(size_t)65536 * 256];
__device__ float g_lepe[(size_t)2 * 128 * 2 * 512 * 64];

// pixel index of window-local token s for branch br, window-local wl
__device__ __forceinline__ int pix_of(int br, int wl, int s) {
    int row, col;
    if (br == 0) { row = s >> 2;            col = wl * 4 + (s & 3); }
    else         { row = wl * 4 + (s >> 7); col = s & 127; }
    return row * 128 + col;
}

// ---------------- LayerNorm: x[B,C,H,W] -> xn[tok][C] ------------------------
__global__ __launch_bounds__(256) void ln_kernel(
    const float* __restrict__ x, const float* __restrict__ g,
    const float* __restrict__ be, float* __restrict__ xn)
{
    __shared__ float xt[256 * 33];
    int b  = blockIdx.x >> 9;
    int p0 = (blockIdx.x & 511) * 32;
    int tid = threadIdx.x, lane = tid & 31, wp = tid >> 5;
    const float* xb = x + (size_t)b * 256 * HW + p0;
#pragma unroll
    for (int it = 0; it < 32; it++) {
        int c = it * 8 + wp;
        xt[c * 33 + lane] = xb[(size_t)c * HW + lane];
    }
    __syncthreads();
    for (int u = 0; u < 4; u++) {
        int p = wp * 4 + u;
        float v[8], sum = 0.f, sq = 0.f;
#pragma unroll
        for (int k = 0; k < 8; k++) {
            float t = xt[(lane + 32 * k) * 33 + p];
            v[k] = t; sum += t; sq += t * t;
        }
#pragma unroll
        for (int o = 16; o; o >>= 1) {
            sum += __shfl_xor_sync(0xffffffffu, sum, o);
            sq  += __shfl_xor_sync(0xffffffffu, sq,  o);
        }
        float mu = sum * (1.f / 256.f);
        float rs = rsqrtf(sq * (1.f / 256.f) - mu * mu + 1e-4f);
        size_t tokb = ((size_t)b * HW + p0 + p) * 256;
#pragma unroll
        for (int k = 0; k < 8; k++) {
            int c = lane + 32 * k;
            xn[tokb + c] = (v[k] - mu) * rs * g[c] + be[c];
        }
    }
}

// ---------------- fp32 SGEMM: C[M,N] = A[M,K] @ B[K,N] (+bias[m]) -----------
// 128x128 block tile, 16 k-depth, 256 threads, 8x8 microtile, reg prefetch.
__global__ __launch_bounds__(256) void sgemm_kernel(
    const float* __restrict__ A, const float* __restrict__ B,
    float* __restrict__ C, const float* __restrict__ bias,
    int M, int N, int K, int lda, int ldb, int ldc,
    size_t sA, size_t sB, size_t sC)
{
    __shared__ float As[16 * 132];   // [k][m]
    __shared__ float Bs[16 * 132];   // [k][n]
    A += (size_t)blockIdx.z * sA;
    B += (size_t)blockIdx.z * sB;
    C += (size_t)blockIdx.z * sC;
    int m0 = blockIdx.y * 128, n0 = blockIdx.x * 128;
    int tid = threadIdx.x, tx = tid & 15, ty = tid >> 4;

    float4 pa[2], pb[2];
    auto loadg = [&](int k0) {
#pragma unroll
        for (int s = 0; s < 2; s++) {
            int f4 = tid + 256 * s;
            pa[s] = *(const float4*)&A[(size_t)(m0 + (f4 >> 2)) * lda + k0 + (f4 & 3) * 4];
            pb[s] = *(const float4*)&B[(size_t)(k0 + (f4 >> 5)) * ldb + n0 + (f4 & 31) * 4];
        }
    };
    auto store_s = [&]() {
#pragma unroll
        for (int s = 0; s < 2; s++) {
            int f4 = tid + 256 * s; int row = f4 >> 2, kq = f4 & 3;
            As[(kq * 4 + 0) * 132 + row] = pa[s].x;
            As[(kq * 4 + 1) * 132 + row] = pa[s].y;
            As[(kq * 4 + 2) * 132 + row] = pa[s].z;
            As[(kq * 4 + 3) * 132 + row] = pa[s].w;
            *(float4*)&Bs[(f4 >> 5) * 132 + (f4 & 31) * 4] = pb[s];
        }
    };

    float acc[8][8];
#pragma unroll
    for (int i = 0; i < 8; i++)
#pragma unroll
        for (int j = 0; j < 8; j++) acc[i][j] = 0.f;

    loadg(0); store_s(); __syncthreads();
    for (int k0 = 16; k0 <= K; k0 += 16) {
        if (k0 < K) loadg(k0);
#pragma unroll
        for (int k = 0; k < 16; k++) {
            float a[8], bv[8];
            *(float4*)&a[0]  = *(const float4*)&As[k * 132 + ty * 8];
            *(float4*)&a[4]  = *(const float4*)&As[k * 132 + ty * 8 + 4];
            *(float4*)&bv[0] = *(const float4*)&Bs[k * 132 + tx * 8];
            *(float4*)&bv[4] = *(const float4*)&Bs[k * 132 + tx * 8 + 4];
#pragma unroll
            for (int i = 0; i < 8; i++)
#pragma unroll
                for (int j = 0; j < 8; j++) acc[i][j] = fmaf(a[i], bv[j], acc[i][j]);
        }
        __syncthreads();
        if (k0 < K) { store_s(); __syncthreads(); }
    }
#pragma unroll
    for (int i = 0; i < 8; i++) {
        size_t m = m0 + ty * 8 + i;
        float bv = bias ? bias[m] : 0.f;
        float4 c0, c1;
        c0.x = acc[i][0] + bv; c0.y = acc[i][1] + bv;
        c0.z = acc[i][2] + bv; c0.w = acc[i][3] + bv;
        c1.x = acc[i][4] + bv; c1.y = acc[i][5] + bv;
        c1.z = acc[i][6] + bv; c1.w = acc[i][7] + bv;
        float* cp = &C[m * ldc + n0 + tx * 8];
        *(float4*)cp = c0; *(float4*)(cp + 4) = c1;
    }
}

// ---------------- LePE: depthwise 3x3 per window, both branches --------------
__global__ __launch_bounds__(256) void lepe_kernel(
    const float* __restrict__ qkv,
    const float* __restrict__ w1, const float* __restrict__ b1,
    const float* __restrict__ w2, const float* __restrict__ b2,
    float* __restrict__ lepe)
{
    extern __shared__ float vbuf[];   // [512][33]
    int br = blockIdx.x >> 7, win = blockIdx.x & 127;
    int b = win >> 5, wl = win & 31;
    const float* w  = br ? w2 : w1;
    const float* bb = br ? b2 : b1;
    int tid = threadIdx.x;
    int hsp = br ? 4 : 128, wsp = br ? 128 : 4;
    int voff = 512 + br * 128;

    for (int ch0 = 0; ch0 < 128; ch0 += 32) {
        __syncthreads();
        for (int idx = tid; idx < 512 * 32; idx += 256) {
            int s = idx >> 5, c = idx & 31;
            size_t tok = (size_t)b * HW + pix_of(br, wl, s);
            vbuf[s * 33 + c] = qkv[tok * 768 + voff + ch0 + c];
        }
        __syncthreads();
        int c = tid & 31, cf = ch0 + c;
        float wr[9];
#pragma unroll
        for (int kk = 0; kk < 9; kk++) wr[kk] = w[cf * 9 + kk];
        float bv = bb[cf];
        size_t obase = ((size_t)(br * 128 + win) * 2 + (cf & 1)) * 512 * 64 + (cf >> 1);
        int sb = (tid >> 5) * 64;
        for (int t = 0; t < 64; t++) {
            int s = sb + t;
            int i = br ? (s >> 7) : (s >> 2);
            int j = br ? (s & 127) : (s & 3);
            float acc = bv;
#pragma unroll
            for (int di = 0; di < 3; di++) {
                int ii = i + di - 1;
                if (ii < 0 || ii >= hsp) continue;
#pragma unroll
                for (int dj = 0; dj < 3; dj++) {
                    int jj = j + dj - 1;
                    if (jj < 0 || jj >= wsp) continue;
                    acc = fmaf(vbuf[(ii * wsp + jj) * 33 + c], wr[di * 3 + dj], acc);
                }
            }
            lepe[obase + (size_t)s * 64] = acc;
        }
    }
}

// ---------------- flash attention per (br, win, head, 128-query tile) --------
__global__ __launch_bounds__(256) void attn_kernel(
    const float* __restrict__ qkv, const float* __restrict__ lepe,
    float* __restrict__ xc)
{
    extern __shared__ float sm[];
    float* Qs = sm;                 // [128][65]
    float* Ks = Qs + 128 * 65;      // [64][65]
    float* Vs = Ks + 64 * 65;       // [64][65]
    float* Ps = Vs + 64 * 65;       // [128][65]
    int bx = blockIdx.x;
    int qt = bx & 3, head = (bx >> 2) & 1, win = (bx >> 3) & 127, br = bx >> 10;
    int b = win >> 5, wl = win & 31;
    int tid = threadIdx.x, cg = tid & 15, rg = tid >> 4;
    int coff = br * 128 + head;
    const float qscale = 0.08838834764831845f * 1.4426950408889634f; // SCALE*log2e

    for (int idx = tid; idx < 128 * 64; idx += 256) {
        int r = idx >> 6, d = idx & 63;
        size_t tok = (size_t)b * HW + pix_of(br, wl, qt * 128 + r);
        Qs[r * 65 + d] = qkv[tok * 768 + coff + d * 2] * qscale;
    }
    float o[8][4], m[8], l[8];
#pragma unroll
    for (int i = 0; i < 8; i++) {
        m[i] = -1e30f; l[i] = 0.f;
#pragma unroll
        for (int j = 0; j < 4; j++) o[i][j] = 0.f;
    }

    for (int kt = 0; kt < 8; kt++) {
        __syncthreads();   // previous PV done before overwriting Ks/Vs
        for (int idx = tid; idx < 64 * 64; idx += 256) {
            int t = idx >> 6, d = idx & 63;
            size_t tok = (size_t)b * HW + pix_of(br, wl, kt * 64 + t);
            const float* qp = qkv + tok * 768 + coff + d * 2;
            Ks[t * 65 + d] = qp[256];
            Vs[t * 65 + d] = qp[512];
        }
        __syncthreads();

        float sacc[8][4];
#pragma unroll
        for (int i = 0; i < 8; i++)
#pragma unroll
            for (int j = 0; j < 4; j++) sacc[i][j] = 0.f;
#pragma unroll 4
        for (int k = 0; k < 64; k++) {
            float kv[4];
#pragma unroll
            for (int j = 0; j < 4; j++) kv[j] = Ks[(cg * 4 + j) * 65 + k];
#pragma unroll
            for (int i = 0; i < 8; i++) {
                float qv = Qs[(rg * 8 + i) * 65 + k];
#pragma unroll
                for (int j = 0; j < 4; j++) sacc[i][j] = fmaf(qv, kv[j], sacc[i][j]);
            }
        }
        // online softmax (row groups of 16 threads; xor<=8 stays in half-warp)
#pragma unroll
        for (int i = 0; i < 8; i++) {
            float mx = fmaxf(fmaxf(sacc[i][0], sacc[i][1]), fmaxf(sacc[i][2], sacc[i][3]));
#pragma unroll
            for (int off = 8; off; off >>= 1) mx = fmaxf(mx, __shfl_xor_sync(0xffffffffu, mx, off));
            float mn = fmaxf(m[i], mx);
            float f = exp2f(m[i] - mn);
            m[i] = mn;
            float ps = 0.f, p[4];
#pragma unroll
            for (int j = 0; j < 4; j++) { p[j] = exp2f(sacc[i][j] - mn); ps += p[j]; }
#pragma unroll
            for (int off = 8; off; off >>= 1) ps += __shfl_xor_sync(0xffffffffu, ps, off);
            l[i] = l[i] * f + ps;
#pragma unroll
            for (int j = 0; j < 4; j++) { o[i][j] *= f; Ps[(rg * 8 + i) * 65 + cg * 4 + j] = p[j]; }
        }
        __syncthreads();
#pragma unroll 4
        for (int k = 0; k < 64; k++) {
            float vv[4];
#pragma unroll
            for (int j = 0; j < 4; j++) vv[j] = Vs[k * 65 + cg * 4 + j];
#pragma unroll
            for (int i = 0; i < 8; i++) {
                float pv = Ps[(rg * 8 + i) * 65 + k];
#pragma unroll
                for (int j = 0; j < 4; j++) o[i][j] = fmaf(pv, vv[j], o[i][j]);
            }
        }
    }
    // epilogue: /l, + lepe, write xc[b][c][pix]
    size_t lbase = ((size_t)(br * 128 + win) * 2 + head) * 512 * 64;
#pragma unroll
    for (int i = 0; i < 8; i++) {
        int s = qt * 128 + rg * 8 + i;
        float inv = 1.f / l[i];
        float4 lp = *(const float4*)&lepe[lbase + (size_t)s * 64 + cg * 4];
        int pv = pix_of(br, wl, s);
        size_t obase = (size_t)b * 256 * HW + pv;
        int c0 = br * 128 + (cg * 4) * 2 + head;
        xc[obase + (size_t)(c0    ) * HW] = o[i][0] * inv + lp.x;
        xc[obase + (size_t)(c0 + 2) * HW] = o[i][1] * inv + lp.y;
        xc[obase + (size_t)(c0 + 4) * HW] = o[i][2] * inv + lp.z;
        xc[obase + (size_t)(c0 + 6) * HW] = o[i][3] * inv + lp.w;
    }
}

// ---------------- launch ------------------------------------------------------
extern "C" void kernel_launch(void* const* d_in, const int* in_sizes, int n_in,
                              void* d_out, int out_size)
{
    const float* x    = (const float*)d_in[0];
    const float* lng  = (const float*)d_in[1];
    const float* lnb  = (const float*)d_in[2];
    const float* wqkv = (const float*)d_in[3];
    const float* lw1  = (const float*)d_in[4];
    const float* lb1  = (const float*)d_in[5];
    const float* lw2  = (const float*)d_in[6];
    const float* lb2  = (const float*)d_in[7];
    const float* pw   = (const float*)d_in[8];
    const float* pb   = (const float*)d_in[9];
    float* out = (float*)d_out;

    float *xn, *qkv, *xc, *lp;
    cudaGetSymbolAddress((void**)&xn,  g_xn);
    cudaGetSymbolAddress((void**)&qkv, g_qkv);
    cudaGetSymbolAddress((void**)&xc,  g_xc);
    cudaGetSymbolAddress((void**)&lp,  g_lepe);

    cudaFuncSetAttribute(attn_kernel, cudaFuncAttributeMaxDynamicSharedMemorySize, 384 * 65 * 4);
    cudaFuncSetAttribute(lepe_kernel, cudaFuncAttributeMaxDynamicSharedMemorySize, 512 * 33 * 4);

    // 1) LayerNorm -> xn[tok][256]
    ln_kernel<<<2048, 256>>>(x, lng, lnb, xn);
    // 2) qkv[tok][768] = xn @ w_qkv
    sgemm_kernel<<<dim3(6, 512, 1), 256>>>(xn, wqkv, qkv, nullptr,
        65536, 768, 256, 256, 768, 768, 0, 0, 0);
    // 3) LePE per (branch, window)
    lepe_kernel<<<256, 256, 512 * 33 * 4>>>(qkv, lw1, lb1, lw2, lb2, lp);
    // 4) attention -> xc[b][c][pix]
    attn_kernel<<<2048, 256, 384 * 65 * 4>>>(qkv, lp, xc);
    // 5) out[b][o][pix] = proj_w @ xc (+ proj_b), per-batch strided
    sgemm_kernel<<<dim3(128, 2, 4), 256>>>(pw, xc, out, pb,
        256, 16384, 256, 256, 16384, 16384, 0, (size_t)256 * HW, (size_t)256 * HW);
}